// round 3
// baseline (speedup 1.0000x reference)
#include <cuda_runtime.h>
#include <cstdint>
#include <cstddef>

#define BB 256
#define TT 512
#define NN 128
#define GO_IDX 1
#define EOS_IDX 2
#define NEGV -10000.0f

// per-(b,t) log-softmax stats
__device__ float g_m [BB * TT];
__device__ float g_ls[BB * TT];

// lengths dtype self-detection: int64 little-endian => word[1] is high word of
// lengths[0] == 0 (values in [T/2, T]); int32 => lengths[1] != 0.
__device__ __forceinline__ int load_len(const void* lp, int b) {
    const int* p32 = (const int*)lp;
    if (p32[1] == 0) return (int)((const long long*)lp)[b];
    return p32[b];
}

// FFMA-pipe exp, ~1e-9 rel for x in [-87, 0]. Avoids MUFU throughput wall.
__device__ __forceinline__ float fexp(float x) {
    float t  = fmaf(x, 1.4426950408889634f, 12582912.0f);   // round-to-nearest int
    int   ni = __float_as_int(t) - 0x4B400000;              // bits(12582912.0f)
    float n  = t - 12582912.0f;
    float r  = fmaf(n, -0.693359375f, x);                   // ln2_hi
    r        = fmaf(n,  2.12194440e-4f, r);                 // ln2_lo correction
    float p  = 1.9841270e-4f;
    p = fmaf(p, r, 1.3888889e-3f);
    p = fmaf(p, r, 8.3333333e-3f);
    p = fmaf(p, r, 4.1666667e-2f);
    p = fmaf(p, r, 1.6666667e-1f);
    p = fmaf(p, r, 0.5f);
    p = fmaf(p, r, 1.0f);
    p = fmaf(p, r, 1.0f);
    int e = ni + 127; if (e < 1) e = 1;                     // clamp (result ~0 anyway)
    return p * __int_as_float(e << 23);
}

// ---------------------------------------------------------------------------
// Kernel 1: per-row (b,t) log-softmax stats. 1 warp per row, same reduction
// shape as the previously-passing kernel (bitwise-identical m).
// ---------------------------------------------------------------------------
__global__ __launch_bounds__(256)
void lse_kernel(const float* __restrict__ unaries)
{
    const int row  = blockIdx.x * 8 + (threadIdx.x >> 5);
    const int lane = threadIdx.x & 31;
    float4 uv = ((const float4*)(unaries + (size_t)row * NN))[lane];
    float m = fmaxf(fmaxf(uv.x, uv.y), fmaxf(uv.z, uv.w));
    #pragma unroll
    for (int off = 16; off; off >>= 1)
        m = fmaxf(m, __shfl_xor_sync(0xffffffffu, m, off));
    float s = fexp(uv.x - m) + fexp(uv.y - m) + fexp(uv.z - m) + fexp(uv.w - m);
    #pragma unroll
    for (int off = 16; off; off >>= 1)
        s += __shfl_xor_sync(0xffffffffu, s, off);
    if (lane == 0) { g_m[row] = m; g_ls[row] = logf(s); }
}

// ---------------------------------------------------------------------------
// Kernel 2: fused forward + in-CTA backtrace. 1 CTA per batch, 512 threads.
// tid = cur*4 + g : thread owns tag 'cur' and prev-quarter g (32 prev tags).
// trans held in registers (loop-invariant). alphas double-buffered in smem
// (1 barrier/step). Backpointers (uint8) kept in smem; chase is a 30cyc/step
// smem pointer-walk tail instead of a 330us second kernel.
// ---------------------------------------------------------------------------
#define FWD_SMEM (65536 + 1024 + 64)

__global__ __launch_bounds__(512, 2)
void viterbi_fused_kernel(const float* __restrict__ unaries,
                          const float* __restrict__ trans,
                          const void*  __restrict__ lengths,
                          void* __restrict__ outv, int mode)
{
    extern __shared__ char smem[];
    unsigned char* bp_sh = (unsigned char*)smem;       // [TT][NN] uint8 = 64KB
    float*         abuf  = (float*)(smem + 65536);     // 2 x 128 alphas

    const int b   = blockIdx.x;
    const int tid = threadIdx.x;
    const int cur = tid >> 2;
    const int g   = tid & 3;
    const int L   = load_len(lengths, b);

    // loop-invariant transition scores for (cur, prev in [g*32, g*32+32))
    float4 tr[8];
    #pragma unroll
    for (int j = 0; j < 8; ++j)
        tr[j] = *(const float4*)(trans + cur * NN + g * 32 + j * 4);

    // init alphas (log_softmax of {0@GO, -1e4} is identity)
    if (tid < 128) abuf[tid] = (tid == GO_IDX) ? 0.0f : NEGV;
    __syncthreads();

    const float* urow = unaries + (size_t)b * TT * NN;
    const float* gm   = g_m  + b * TT;
    const float* gls  = g_ls + b * TT;
    const float  NI   = __int_as_float(0xff800000);

    for (int t = 0; t < L; ++t) {
        // issue loads early; consumed at end of step (latency hidden)
        float u = 0.f, mm = 0.f, lls = 0.f;
        if (g == 0) {
            u   = __ldg(urow + (size_t)t * NN + cur);
            mm  = __ldg(gm  + t);
            lls = __ldg(gls + t);
        }
        const float* aS = abuf + (t & 1) * 128;

        // 2 independent compare-select chains (in-order => first-index ties)
        float b0 = NI, b1 = NI; int i0 = 0, i1 = 0;
        #pragma unroll
        for (int j = 0; j < 8; ++j) {
            float4 a = ((const float4*)aS)[g * 8 + j];   // broadcast LDS
            float v0 = a.x + tr[j].x;
            float v1 = a.y + tr[j].y;
            float v2 = a.z + tr[j].z;
            float v3 = a.w + tr[j].w;
            if (v0 > b0) { b0 = v0; i0 = j * 4 + 0; }
            if (v1 > b1) { b1 = v1; i1 = j * 4 + 1; }
            if (v2 > b0) { b0 = v2; i0 = j * 4 + 2; }
            if (v3 > b1) { b1 = v3; i1 = j * 4 + 3; }
        }
        float bv = b0; int bi = i0;
        if (b1 > bv || (b1 == bv && i1 < bi)) { bv = b1; bi = i1; }
        bi += g * 32;

        // combine the 4 prev-quarters (adjacent lanes), first-index tie-break
        #pragma unroll
        for (int off = 1; off <= 2; off <<= 1) {
            float ov = __shfl_xor_sync(0xffffffffu, bv, off);
            int   oi = __shfl_xor_sync(0xffffffffu, bi, off);
            if (ov > bv || (ov == bv && oi < bi)) { bv = ov; bi = oi; }
        }

        if (g == 0) {
            float p = (u - mm) - lls;                    // exact passing formula
            abuf[((t + 1) & 1) * 128 + cur] = bv + p;
            bp_sh[t * NN + cur] = (unsigned char)bi;
        }
        __syncthreads();
    }

    float* outf = (float*)outv;
    int*   outi = (int*)outv;
    const int wid = tid >> 5;

    if (wid == 0) {
        // terminal argmax over prev: alpha_{L-1} + trans[EOS]
        const float* aF = abuf + (L & 1) * 128;
        const int lane  = tid;
        float4 a  = ((const float4*)aF)[lane];
        float4 te = ((const float4*)(trans + EOS_IDX * NN))[lane];
        float bv = a.x + te.x; int bi = lane * 4;
        float c;
        c = a.y + te.y; if (c > bv) { bv = c; bi = lane * 4 + 1; }
        c = a.z + te.z; if (c > bv) { bv = c; bi = lane * 4 + 2; }
        c = a.w + te.w; if (c > bv) { bv = c; bi = lane * 4 + 3; }
        #pragma unroll
        for (int off = 16; off; off >>= 1) {
            float ov = __shfl_xor_sync(0xffffffffu, bv, off);
            int   oi = __shfl_xor_sync(0xffffffffu, bi, off);
            if (ov > bv || (ov == bv && oi < bi)) { bv = ov; bi = oi; }
        }
        if (lane == 0) {
            int curt = bi;
            if (mode) { outf[b * TT + (L - 1)] = (float)curt; outf[BB * TT + b] = bv; }
            else      { outi[b * TT + (L - 1)] = curt; }
            for (int t2 = L - 1; t2 >= 1; --t2) {        // smem pointer chase
                curt = bp_sh[t2 * NN + curt];
                if (mode) outf[b * TT + t2 - 1] = (float)curt;
                else      outi[b * TT + t2 - 1] = curt;
            }
        }
    } else if (wid == 1) {
        // zero-fill masked region t >= L (runs concurrently with the chase)
        for (int t2 = L + (tid & 31); t2 < TT; t2 += 32) {
            if (mode) outf[b * TT + t2] = 0.0f; else outi[b * TT + t2] = 0;
        }
    }
}

extern "C" void kernel_launch(void* const* d_in, const int* in_sizes, int n_in,
                              void* d_out, int out_size)
{
    const float* unaries = (const float*)d_in[0];
    const float* trans   = (const float*)d_in[1];
    const void*  lengths = d_in[2];

    cudaFuncSetAttribute(viterbi_fused_kernel,
                         cudaFuncAttributeMaxDynamicSharedMemorySize, FWD_SMEM);

    const int mode = (out_size == BB * TT + BB) ? 1 : 0;

    lse_kernel<<<(BB * TT) / 8, 256>>>(unaries);
    viterbi_fused_kernel<<<BB, 512, FWD_SMEM>>>(unaries, trans, lengths, d_out, mode);
}

// round 6
// speedup vs baseline: 1.5582x; 1.5582x over previous
#include <cuda_runtime.h>
#include <cstdint>
#include <cstddef>

#define BB 256
#define TT 512
#define NN 128
#define GO_IDX 1
#define EOS_IDX 2
#define NEGV -10000.0f
#define FULLM 0xffffffffu
#define PADS 36   // padded stride (floats) per 32-float group: banks differ per group

__device__ float g_alpha[(size_t)BB * TT * NN];   // alpha_t rows
__device__ float g_mval [(size_t)BB * TT * NN];   // pre-unary max rows
__device__ float g_m [BB * TT];
__device__ float g_ls[BB * TT];
__device__ float g_score[BB];
__device__ int   g_bestTag[BB];

// lengths dtype self-detection: int64 LE => word[1] is high word of lengths[0]==0.
__device__ __forceinline__ int load_len(const void* lp, int b) {
    const int* p32 = (const int*)lp;
    if (p32[1] == 0) return (int)((const long long*)lp)[b];
    return p32[b];
}

// FFMA-pipe exp (~1e-9 rel on [-87,0]); avoids MUFU throughput wall.
__device__ __forceinline__ float fexp(float x) {
    float t  = fmaf(x, 1.4426950408889634f, 12582912.0f);
    int   ni = __float_as_int(t) - 0x4B400000;
    float n  = t - 12582912.0f;
    float r  = fmaf(n, -0.693359375f, x);
    r        = fmaf(n,  2.12194440e-4f, r);
    float p  = 1.9841270e-4f;
    p = fmaf(p, r, 1.3888889e-3f);
    p = fmaf(p, r, 8.3333333e-3f);
    p = fmaf(p, r, 4.1666667e-2f);
    p = fmaf(p, r, 1.6666667e-1f);
    p = fmaf(p, r, 0.5f);
    p = fmaf(p, r, 1.0f);
    p = fmaf(p, r, 1.0f);
    int e = ni + 127; if (e < 1) e = 1;
    return p * __int_as_float(e << 23);
}

// ---------------------------------------------------------------------------
// Kernel 1: per-(b,t) log-softmax stats, 1 warp/row (bitwise-identical m to R2).
// ---------------------------------------------------------------------------
__global__ __launch_bounds__(256)
void lse_kernel(const float* __restrict__ unaries)
{
    const int row  = blockIdx.x * 8 + (threadIdx.x >> 5);
    const int lane = threadIdx.x & 31;
    float4 uv = ((const float4*)(unaries + (size_t)row * NN))[lane];
    float m = fmaxf(fmaxf(uv.x, uv.y), fmaxf(uv.z, uv.w));
    #pragma unroll
    for (int off = 16; off; off >>= 1)
        m = fmaxf(m, __shfl_xor_sync(FULLM, m, off));
    float s = fexp(uv.x - m) + fexp(uv.y - m) + fexp(uv.z - m) + fexp(uv.w - m);
    #pragma unroll
    for (int off = 16; off; off >>= 1)
        s += __shfl_xor_sync(FULLM, s, off);
    if (lane == 0) { g_m[row] = m; g_ls[row] = logf(s); }
}

// ---------------------------------------------------------------------------
// Kernel 2: forward, pure max (no argmax). 1 CTA/batch, 512 threads,
// tid = cur*4 + g. Trans in registers; alpha double-buffered in padded smem
// (conflict-free); 1 barrier/step. Stores alpha_t and m_t rows to gmem.
// ---------------------------------------------------------------------------
__global__ __launch_bounds__(512, 2)
void viterbi_forward(const float* __restrict__ unaries,
                     const float* __restrict__ trans,
                     const void*  __restrict__ lengths)
{
    __shared__ float abuf[2][4 * PADS];
    __shared__ float red[16];

    const int b   = blockIdx.x;
    const int tid = threadIdx.x;
    const int cur = tid >> 2;
    const int g   = tid & 3;
    const int L   = load_len(lengths, b);

    // loop-invariant transition scores: prev in [g*32, g*32+32) for this cur
    float4 tr[8];
    #pragma unroll
    for (int j = 0; j < 8; ++j)
        tr[j] = *(const float4*)(trans + cur * NN + g * 32 + j * 4);

    if (g == 0)
        abuf[0][(cur >> 5) * PADS + (cur & 31)] = (cur == GO_IDX) ? 0.0f : NEGV;
    __syncthreads();

    const float* urow = unaries + (size_t)b * TT * NN;
    const float* gmp  = g_m  + b * TT;
    const float* glp  = g_ls + b * TT;
    float* aout = g_alpha + (size_t)b * TT * NN;
    float* mout = g_mval  + (size_t)b * TT * NN;

    for (int t = 0; t < L; ++t) {
        float u = 0.f, mm = 0.f, lls = 0.f;
        if (g == 0) {
            u   = __ldg(urow + (size_t)t * NN + cur);
            mm  = __ldg(gmp + t);
            lls = __ldg(glp + t);
        }
        const float* aS = abuf[t & 1] + g * PADS;   // bank-disjoint per g

        float mj[8];
        #pragma unroll
        for (int j = 0; j < 8; ++j) {
            float4 a = *(const float4*)(aS + j * 4);
            float v0 = a.x + tr[j].x;
            float v1 = a.y + tr[j].y;
            float v2 = a.z + tr[j].z;
            float v3 = a.w + tr[j].w;
            mj[j] = fmaxf(fmaxf(v0, v1), fmaxf(v2, v3));
        }
        float m01 = fmaxf(mj[0], mj[1]), m23 = fmaxf(mj[2], mj[3]);
        float m45 = fmaxf(mj[4], mj[5]), m67 = fmaxf(mj[6], mj[7]);
        float bv  = fmaxf(fmaxf(m01, m23), fmaxf(m45, m67));
        bv = fmaxf(bv, __shfl_xor_sync(FULLM, bv, 1));
        bv = fmaxf(bv, __shfl_xor_sync(FULLM, bv, 2));

        if (g == 0) {
            float a = bv + ((u - mm) - lls);          // exact passing formula
            abuf[(t + 1) & 1][(cur >> 5) * PADS + (cur & 31)] = a;
            aout[(size_t)t * NN + cur] = a;
            mout[(size_t)t * NN + cur] = bv;
        }
        __syncthreads();
    }

    // terminal argmax over prev (first-index), warp 0 only
    if (tid < 32) {
        const float* aF = abuf[L & 1];
        float bv = __int_as_float(0xff800000); int bi = 0;
        #pragma unroll
        for (int k = 0; k < 4; ++k) {
            int c = tid * 4 + k;
            float v = aF[(c >> 5) * PADS + (c & 31)] + __ldg(trans + EOS_IDX * NN + c);
            if (v > bv) { bv = v; bi = c; }           // in-order: first-index ties
        }
        #pragma unroll
        for (int off = 16; off; off >>= 1) {
            float ov = __shfl_xor_sync(FULLM, bv, off);
            int   oi = __shfl_xor_sync(FULLM, bi, off);
            if (ov > bv || (ov == bv && oi < bi)) { bv = ov; bi = oi; }
        }
        if (tid == 0) { g_score[b] = bv; g_bestTag[b] = bi; }
    }
    (void)red;
}

// ---------------------------------------------------------------------------
// Kernel 3: backtrace via equality against stored m. 1 warp/batch,
// 32 CTAs x 256 threads. Full trans in smem; alpha/m rows prefetched 2 ahead.
// Per-step chain: LDS(trans row) + FADD + FSETP + ballot + ffs + shfl.
// ---------------------------------------------------------------------------
#define BT_SMEM (65536 + 8 * TT * 4)

__global__ __launch_bounds__(256)
void viterbi_backtrace(const float* __restrict__ trans,
                       const void*  __restrict__ lengths,
                       void* __restrict__ outv, int mode)
{
    extern __shared__ char smem[];
    float4* trS  = (float4*)smem;                 // [128][32] float4
    int*    path = (int*)(smem + 65536);          // [8][TT]

    const int tid = threadIdx.x;
    for (int i = tid; i < 128 * 32; i += 256)
        trS[i] = ((const float4*)trans)[i];
    __syncthreads();

    const int w    = tid >> 5;
    const int lane = tid & 31;
    const int b    = blockIdx.x * 8 + w;
    const int L    = load_len(lengths, b);
    int cur = g_bestTag[b];
    int* mypath = path + w * TT;
    if (lane == 0) mypath[L - 1] = cur;

    const float4* arow = (const float4*)(g_alpha + (size_t)b * TT * NN);
    const float4* mrow = (const float4*)(g_mval  + (size_t)b * TT * NN);

    // iteration t (from t0=L-1 down to 1) uses arow[t-1] and mrow[t]
    const int t0 = L - 1;
    float4 ab0, ab1, mb0, mb1;
    ab0 = ab1 = mb0 = mb1 = make_float4(0.f, 0.f, 0.f, 0.f);
    if (t0 >= 1) { ab0 = arow[(size_t)(t0 - 1) * 32 + lane]; mb0 = mrow[(size_t)t0 * 32 + lane]; }
    if (t0 >= 2) { ab1 = arow[(size_t)(t0 - 2) * 32 + lane]; mb1 = mrow[(size_t)(t0 - 1) * 32 + lane]; }

    for (int t = t0; t >= 1; --t) {
        const int par = (t0 - t) & 1;
        float4 av = par ? ab1 : ab0;
        float4 mv = par ? mb1 : mb0;
        if (t >= 3) {   // prefetch for iteration t-2 into the buffer just consumed
            float4 na = arow[(size_t)(t - 3) * 32 + lane];
            float4 nm = mrow[(size_t)(t - 2) * 32 + lane];
            if (par) { ab1 = na; mb1 = nm; } else { ab0 = na; mb0 = nm; }
        }
        // exact max value for this (t, cur): extract from lane cur>>2, comp cur&3
        const int sl   = cur >> 2;
        const int comp = cur & 3;
        float mc = (comp == 0) ? mv.x : (comp == 1) ? mv.y : (comp == 2) ? mv.z : mv.w;
        float mstar = __shfl_sync(FULLM, mc, sl);

        float4 tv = trS[cur * 32 + lane];
        float v0 = av.x + tv.x, v1 = av.y + tv.y;
        float v2 = av.z + tv.z, v3 = av.w + tv.w;
        bool e0 = (v0 == mstar), e1 = (v1 == mstar);
        bool e2 = (v2 == mstar), e3 = (v3 == mstar);
        unsigned mask = __ballot_sync(FULLM, e0 | e1 | e2 | e3);
        int wl = __ffs(mask) - 1;
        int lj = 3; if (e2) lj = 2; if (e1) lj = 1; if (e0) lj = 0;  // first local idx
        int ljw = __shfl_sync(FULLM, lj, wl);
        cur = wl * 4 + ljw;
        if (lane == 0) mypath[t - 1] = cur;
    }
    __syncwarp();

    float* outf = (float*)outv;
    int*   outi = (int*)outv;
    for (int tt = lane; tt < TT; tt += 32) {
        int v = (tt < L) ? mypath[tt] : 0;
        if (mode) outf[b * TT + tt] = (float)v;
        else      outi[b * TT + tt] = v;
    }
    if (mode && lane == 0) outf[BB * TT + b] = g_score[b];
}

extern "C" void kernel_launch(void* const* d_in, const int* in_sizes, int n_in,
                              void* d_out, int out_size)
{
    const float* unaries = (const float*)d_in[0];
    const float* trans   = (const float*)d_in[1];
    const void*  lengths = d_in[2];

    cudaFuncSetAttribute(viterbi_backtrace,
                         cudaFuncAttributeMaxDynamicSharedMemorySize, BT_SMEM);

    const int mode = (out_size == BB * TT + BB) ? 1 : 0;

    lse_kernel<<<(BB * TT) / 8, 256>>>(unaries);
    viterbi_forward<<<BB, 512>>>(unaries, trans, lengths);
    viterbi_backtrace<<<32, 256, BT_SMEM>>>(trans, lengths, d_out, mode);
}